// round 1
// baseline (speedup 1.0000x reference)
#include <cuda_runtime.h>
#include <cstdint>

#define Bq 4
#define Mq 8192
#define Nq 8192
#define Kq 8
#define Fq 288
#define NODESQ (Mq + Nq)        // 16384
#define ROWSQ (Bq * Mq)         // 32768

// Scratch (static device globals — no allocations allowed)
__device__ float g_agg[(size_t)ROWSQ * Fq];     // 37.7 MB
__device__ float g_h1[(size_t)ROWSQ * Fq];      // 37.7 MB
__device__ int   g_deg[Bq * NODESQ];
__device__ float g_dsc[Bq * NODESQ];            // deg_out^-1/2 (clipped)
__device__ float g_style[Fq];                   // relu(b1) == h1 for style nodes

// ---------------------------------------------------------------------------
// 1. zero deg
__global__ void zero_deg_kernel() {
    int i = blockIdx.x * blockDim.x + threadIdx.x;
    if (i < Bq * NODESQ) g_deg[i] = 0;
}

// 2. histogram of src indices
__global__ void hist_kernel(const int* __restrict__ idx_k1,
                            const int* __restrict__ idx_k2) {
    int e = blockIdx.x * blockDim.x + threadIdx.x;   // over B*M*K
    if (e >= Bq * Mq * Kq) return;
    int b = e / (Mq * Kq);
    atomicAdd(&g_deg[b * NODESQ + idx_k2[e]], 1);
    atomicAdd(&g_deg[b * NODESQ + Mq + idx_k1[e]], 1);
}

// 3. dsc = rsqrt(max(deg,1)); also g_style = relu(b1)
__global__ void dsc_kernel(const float* __restrict__ b1) {
    int i = blockIdx.x * blockDim.x + threadIdx.x;
    if (i < Bq * NODESQ) {
        int d = g_deg[i];
        g_dsc[i] = rsqrtf((float)(d > 1 ? d : 1));
    }
    if (i < Fq) g_style[i] = fmaxf(b1[i], 0.0f);
}

// 4. gather layer 1: agg1[b,v,:] = 0.25 * sum_j (feat_c[i2]*s2 + feat_s[i1]*s1)
__global__ __launch_bounds__(Fq) void gather1_kernel(
    const float* __restrict__ feat_c, const float* __restrict__ feat_s,
    const int* __restrict__ idx_k1, const int* __restrict__ idx_k2) {
    int row = blockIdx.x;                // b*M + v
    int b = row / Mq;
    int t = threadIdx.x;

    __shared__ int   sidx[16];
    __shared__ float ssc[16];
    if (t < 8) {
        int i = idx_k2[(size_t)row * Kq + t];
        sidx[t] = i;
        ssc[t]  = g_dsc[b * NODESQ + i];
    } else if (t < 16) {
        int i = idx_k1[(size_t)row * Kq + (t - 8)];
        sidx[t] = i;
        ssc[t]  = g_dsc[b * NODESQ + Mq + i];
    }
    __syncthreads();

    const float* fc = feat_c + (size_t)b * Mq * Fq;
    const float* fs = feat_s + (size_t)b * Nq * Fq;
    float acc = 0.0f;
#pragma unroll
    for (int j = 0; j < 8; j++)
        acc += fc[(size_t)sidx[j] * Fq + t] * ssc[j];
#pragma unroll
    for (int j = 8; j < 16; j++)
        acc += fs[(size_t)sidx[j] * Fq + t] * ssc[j];
    g_agg[(size_t)row * Fq + t] = acc * 0.25f;
}

// 6. gather layer 2: agg2 = 0.25*(sum_j h1[i2]*s2 + (sum_j s1) * style)
__global__ __launch_bounds__(Fq) void gather2_kernel(
    const int* __restrict__ idx_k1, const int* __restrict__ idx_k2) {
    int row = blockIdx.x;
    int b = row / Mq;
    int t = threadIdx.x;

    __shared__ int   sidx[8];
    __shared__ float ssc[8];
    __shared__ float ssty[8];
    if (t < 8) {
        int i = idx_k2[(size_t)row * Kq + t];
        sidx[t] = i;
        ssc[t]  = g_dsc[b * NODESQ + i];
        int i1 = idx_k1[(size_t)row * Kq + t];
        ssty[t] = g_dsc[b * NODESQ + Mq + i1];
    }
    __syncthreads();

    float stySum = 0.0f;
#pragma unroll
    for (int j = 0; j < 8; j++) stySum += ssty[j];

    const float* h1b = g_h1 + (size_t)b * Mq * Fq;
    float acc = stySum * g_style[t];
#pragma unroll
    for (int j = 0; j < 8; j++)
        acc += h1b[(size_t)sidx[j] * Fq + t] * ssc[j];
    g_agg[(size_t)row * Fq + t] = acc * 0.25f;
}

// ---------------------------------------------------------------------------
// GEMM: C[R,288] = A[R,288] @ W[288,288] + bias, optional ReLU.
// Tile 64x96, BK=16, 256 threads, 4x6 per-thread micro tile.
template <bool RELU>
__global__ __launch_bounds__(256) void gemm_bias_kernel(
    const float* __restrict__ A, const float* __restrict__ W,
    const float* __restrict__ bias, float* __restrict__ C) {
    __shared__ float sA[16][64];
    __shared__ float sW[16][96];

    int tid = threadIdx.x;
    int rowBase = blockIdx.x * 64;
    int colBase = blockIdx.y * 96;
    int ty = tid >> 4;        // 0..15
    int tx = tid & 15;        // 0..15

    float acc[4][6];
#pragma unroll
    for (int i = 0; i < 4; i++)
#pragma unroll
        for (int j = 0; j < 6; j++) acc[i][j] = 0.0f;

    int lr = tid >> 2;            // 0..63 (A load row)
    int lk = (tid & 3) * 4;       // k offset within tile

    for (int k0 = 0; k0 < Fq; k0 += 16) {
        // A tile (64x16), float4 loads, stored transposed
        float4 av = *(const float4*)(A + (size_t)(rowBase + lr) * Fq + k0 + lk);
        sA[lk + 0][lr] = av.x;
        sA[lk + 1][lr] = av.y;
        sA[lk + 2][lr] = av.z;
        sA[lk + 3][lr] = av.w;
        // W tile (16x96)
#pragma unroll
        for (int i = 0; i < 6; i++) {
            int e = tid + i * 256;         // 0..1535
            int kr = e / 96, nc = e % 96;
            sW[kr][nc] = W[(size_t)(k0 + kr) * Fq + colBase + nc];
        }
        __syncthreads();
#pragma unroll
        for (int kk = 0; kk < 16; kk++) {
            float a[4], w[6];
#pragma unroll
            for (int i = 0; i < 4; i++) a[i] = sA[kk][ty * 4 + i];
#pragma unroll
            for (int j = 0; j < 6; j++) w[j] = sW[kk][tx * 6 + j];
#pragma unroll
            for (int i = 0; i < 4; i++)
#pragma unroll
                for (int j = 0; j < 6; j++) acc[i][j] = fmaf(a[i], w[j], acc[i][j]);
        }
        __syncthreads();
    }

#pragma unroll
    for (int i = 0; i < 4; i++) {
        int r = rowBase + ty * 4 + i;
#pragma unroll
        for (int j = 0; j < 6; j++) {
            int c = colBase + tx * 6 + j;
            float v = acc[i][j] + bias[c];
            if (RELU) v = fmaxf(v, 0.0f);
            C[(size_t)r * Fq + c] = v;
        }
    }
}

// ---------------------------------------------------------------------------
extern "C" void kernel_launch(void* const* d_in, const int* in_sizes, int n_in,
                              void* d_out, int out_size) {
    const float* feat_c = (const float*)d_in[0];   // [B,M,F]
    const float* feat_s = (const float*)d_in[1];   // [B,N,F]
    const int*   idx_k1 = (const int*)d_in[2];     // [B,M,K]
    const int*   idx_k2 = (const int*)d_in[3];     // [B,M,K]
    const float* W1     = (const float*)d_in[4];   // [F,F]
    const float* b1     = (const float*)d_in[5];   // [F]
    const float* W2     = (const float*)d_in[6];   // [F,F]
    const float* b2     = (const float*)d_in[7];   // [F]
    float* out = (float*)d_out;                    // [B,M,F]

    float* agg; cudaGetSymbolAddress((void**)&agg, g_agg);
    float* h1;  cudaGetSymbolAddress((void**)&h1,  g_h1);

    // degrees
    zero_deg_kernel<<<(Bq * NODESQ + 255) / 256, 256>>>();
    hist_kernel<<<(Bq * Mq * Kq + 255) / 256, 256>>>(idx_k1, idx_k2);
    dsc_kernel<<<(Bq * NODESQ + 255) / 256, 256>>>(b1);

    // layer 1
    gather1_kernel<<<ROWSQ, Fq>>>(feat_c, feat_s, idx_k1, idx_k2);
    {
        dim3 grid(ROWSQ / 64, Fq / 96);
        gemm_bias_kernel<true><<<grid, 256>>>(agg, W1, b1, h1);
    }

    // layer 2
    gather2_kernel<<<ROWSQ, Fq>>>(idx_k1, idx_k2);
    {
        dim3 grid(ROWSQ / 64, Fq / 96);
        gemm_bias_kernel<false><<<grid, 256>>>(agg, W2, b2, out);
    }
}

// round 3
// speedup vs baseline: 1.9616x; 1.9616x over previous
#include <cuda_runtime.h>
#include <cstdint>

#define Bq 4
#define Mq 8192
#define Nq 8192
#define Kq 8
#define Fq 288
#define NODESQ (Mq + Nq)        // 16384
#define ROWSQ (Bq * Mq)         // 32768

// Scratch (static device globals — no allocations allowed)
__device__ float g_agg[(size_t)ROWSQ * Fq];     // 37.7 MB
__device__ float g_h1[(size_t)ROWSQ * Fq];      // 37.7 MB
__device__ float g_Wt1[Fq * Fq];                // W1^T: [N,K] K contiguous
__device__ float g_Wt2[Fq * Fq];                // W2^T
__device__ int   g_deg[Bq * NODESQ];
__device__ float g_dsc[Bq * NODESQ];            // deg_out^-1/2 (clipped)
__device__ float g_style[Fq];                   // relu(b1): h1 of style nodes

// ---------------------------------------------------------------------------
__device__ __forceinline__ uint32_t f2tf32(float x) {
    uint32_t r;
    asm("cvt.rna.tf32.f32 %0, %1;" : "=r"(r) : "f"(x));
    return r;
}

__device__ __forceinline__ void mma_tf32(float* c, const uint32_t* a,
                                         uint32_t b0, uint32_t b1) {
    asm volatile(
        "mma.sync.aligned.m16n8k8.row.col.f32.tf32.tf32.f32 "
        "{%0,%1,%2,%3}, {%4,%5,%6,%7}, {%8,%9}, {%0,%1,%2,%3};"
        : "+f"(c[0]), "+f"(c[1]), "+f"(c[2]), "+f"(c[3])
        : "r"(a[0]), "r"(a[1]), "r"(a[2]), "r"(a[3]), "r"(b0), "r"(b1));
}

// ---------------------------------------------------------------------------
// small prep kernels
// ---------------------------------------------------------------------------
__global__ void zero_deg_kernel() {
    int i = blockIdx.x * blockDim.x + threadIdx.x;
    if (i < Bq * NODESQ) g_deg[i] = 0;
}

__global__ void hist_kernel(const int* __restrict__ idx_k1,
                            const int* __restrict__ idx_k2) {
    int e = blockIdx.x * blockDim.x + threadIdx.x;
    if (e >= Bq * Mq * Kq) return;
    int b = e / (Mq * Kq);
    atomicAdd(&g_deg[b * NODESQ + idx_k2[e]], 1);
    atomicAdd(&g_deg[b * NODESQ + Mq + idx_k1[e]], 1);
}

__global__ void dsc_kernel(const float* __restrict__ b1) {
    int i = blockIdx.x * blockDim.x + threadIdx.x;
    if (i < Bq * NODESQ) {
        int d = g_deg[i];
        g_dsc[i] = rsqrtf((float)(d > 1 ? d : 1));
    }
    if (i < Fq) g_style[i] = fmaxf(b1[i], 0.0f);
}

__global__ void transpose_kernel(const float* __restrict__ W1,
                                 const float* __restrict__ W2) {
    int i = blockIdx.x * blockDim.x + threadIdx.x;
    if (i < Fq * Fq) {
        int k = i / Fq, n = i % Fq;
        g_Wt1[n * Fq + k] = W1[i];
        g_Wt2[n * Fq + k] = W2[i];
    }
}

// ---------------------------------------------------------------------------
// gathers: warp-per-row, float4 gathers with high MLP
// ---------------------------------------------------------------------------
__global__ __launch_bounds__(256) void gather1_kernel(
    const float* __restrict__ feat_c, const float* __restrict__ feat_s,
    const int* __restrict__ idx_k1, const int* __restrict__ idx_k2) {
    int wid = threadIdx.x >> 5, lane = threadIdx.x & 31;
    int row = blockIdx.x * 8 + wid;
    int b = row >> 13;
    const float* srcp = feat_c;
    float sc = 0.0f;
    if (lane < 8) {
        int i = idx_k2[row * Kq + lane];
        sc = g_dsc[b * NODESQ + i];
        srcp = feat_c + ((size_t)b * Mq + i) * Fq;
    } else if (lane < 16) {
        int i = idx_k1[row * Kq + (lane - 8)];
        sc = g_dsc[b * NODESQ + Mq + i];
        srcp = feat_s + ((size_t)b * Nq + i) * Fq;
    }
    unsigned long long pv = (unsigned long long)srcp;
    const float4* p[16];
    float s[16];
#pragma unroll
    for (int j = 0; j < 16; j++) {
        p[j] = (const float4*)__shfl_sync(0xffffffffu, pv, j);
        s[j] = __shfl_sync(0xffffffffu, sc, j);
    }
    float4* outp = (float4*)(g_agg + (size_t)row * Fq);
    for (int c = lane; c < 72; c += 32) {
        float4 a = make_float4(0.f, 0.f, 0.f, 0.f);
#pragma unroll
        for (int j = 0; j < 16; j++) {
            float4 v = __ldg(&p[j][c]);
            a.x = fmaf(v.x, s[j], a.x);
            a.y = fmaf(v.y, s[j], a.y);
            a.z = fmaf(v.z, s[j], a.z);
            a.w = fmaf(v.w, s[j], a.w);
        }
        a.x *= 0.25f; a.y *= 0.25f; a.z *= 0.25f; a.w *= 0.25f;
        outp[c] = a;
    }
}

__global__ __launch_bounds__(256) void gather2_kernel(
    const int* __restrict__ idx_k1, const int* __restrict__ idx_k2) {
    int wid = threadIdx.x >> 5, lane = threadIdx.x & 31;
    int row = blockIdx.x * 8 + wid;
    int b = row >> 13;
    const float* srcp = g_h1;
    float sc = 0.0f, sty = 0.0f;
    if (lane < 8) {
        int i2 = idx_k2[row * Kq + lane];
        sc = g_dsc[b * NODESQ + i2];
        srcp = g_h1 + ((size_t)b * Mq + i2) * Fq;
        int i1 = idx_k1[row * Kq + lane];
        sty = g_dsc[b * NODESQ + Mq + i1];
    }
    unsigned long long pv = (unsigned long long)srcp;
    const float4* p[8];
    float s[8];
    float stySum = 0.0f;
#pragma unroll
    for (int j = 0; j < 8; j++) {
        p[j] = (const float4*)__shfl_sync(0xffffffffu, pv, j);
        s[j] = __shfl_sync(0xffffffffu, sc, j);
        stySum += __shfl_sync(0xffffffffu, sty, j);
    }
    const float4* st = (const float4*)g_style;
    float4* outp = (float4*)(g_agg + (size_t)row * Fq);
    for (int c = lane; c < 72; c += 32) {
        float4 sv = st[c];
        float4 a;
        a.x = stySum * sv.x; a.y = stySum * sv.y;
        a.z = stySum * sv.z; a.w = stySum * sv.w;
#pragma unroll
        for (int j = 0; j < 8; j++) {
            float4 v = __ldg(&p[j][c]);
            a.x = fmaf(v.x, s[j], a.x);
            a.y = fmaf(v.y, s[j], a.y);
            a.z = fmaf(v.z, s[j], a.z);
            a.w = fmaf(v.w, s[j], a.w);
        }
        a.x *= 0.25f; a.y *= 0.25f; a.z *= 0.25f; a.w *= 0.25f;
        outp[c] = a;
    }
}

// ---------------------------------------------------------------------------
// tf32 mma.sync GEMM: C[32768,288] = A[32768,288] @ Bt^T  (+bias, opt ReLU)
// CTA tile 128x96, KC=16, 256 threads (8 warps as 4x2), warp tile 32x48.
// Double-buffered smem, one __syncthreads per K-chunk.
// ---------------------------------------------------------------------------
#define TMg 128
#define TNg 96
#define KCg 16
#define PITCH 20
#define NCHUNK (Fq / KCg)   // 18

template <bool RELU>
__global__ __launch_bounds__(256, 2) void gemm_tf32_kernel(
    const float* __restrict__ A, const float* __restrict__ Bt,
    const float* __restrict__ bias, float* __restrict__ C) {
    __shared__ float As[2][TMg * PITCH];
    __shared__ float Bs[2][TNg * PITCH];

    int tid = threadIdx.x;
    int wid = tid >> 5, lane = tid & 31;
    int wm = wid >> 1, wn = wid & 1;      // 4 x 2 warp grid
    int rowBase = blockIdx.x * TMg;
    int colBase = blockIdx.y * TNg;

    int lr = lane >> 2;                   // 0..7
    int lc = lane & 3;                    // 0..3

    float acc[2][6][4];
#pragma unroll
    for (int i = 0; i < 2; i++)
#pragma unroll
        for (int j = 0; j < 6; j++)
#pragma unroll
            for (int e = 0; e < 4; e++) acc[i][j][e] = 0.0f;

    float4 ra[2], rb0, rb1;
    const bool hasB1 = (tid < 128);

    // ---- load helpers (chunk c covers k in [c*16, c*16+16)) ----
    auto loadG = [&](int c) {
#pragma unroll
        for (int t = 0; t < 2; t++) {
            int i = tid + t * 256;                 // 0..511
            int r = i >> 2, q = i & 3;
            ra[t] = __ldg((const float4*)(A + (size_t)(rowBase + r) * Fq + c * KCg) + q);
        }
        {
            int r = tid >> 2, q = tid & 3;
            rb0 = __ldg((const float4*)(Bt + (size_t)(colBase + r) * Fq + c * KCg) + q);
        }
        if (hasB1) {
            int i = tid + 256;
            int r = i >> 2, q = i & 3;
            rb1 = __ldg((const float4*)(Bt + (size_t)(colBase + r) * Fq + c * KCg) + q);
        }
    };
    auto storeS = [&](int s) {
#pragma unroll
        for (int t = 0; t < 2; t++) {
            int i = tid + t * 256;
            int r = i >> 2, q = i & 3;
            float* d = &As[s][r * PITCH + q * 4];
            d[0] = __uint_as_float(f2tf32(ra[t].x));
            d[1] = __uint_as_float(f2tf32(ra[t].y));
            d[2] = __uint_as_float(f2tf32(ra[t].z));
            d[3] = __uint_as_float(f2tf32(ra[t].w));
        }
        {
            int r = tid >> 2, q = tid & 3;
            float* d = &Bs[s][r * PITCH + q * 4];
            d[0] = __uint_as_float(f2tf32(rb0.x));
            d[1] = __uint_as_float(f2tf32(rb0.y));
            d[2] = __uint_as_float(f2tf32(rb0.z));
            d[3] = __uint_as_float(f2tf32(rb0.w));
        }
        if (hasB1) {
            int i = tid + 256;
            int r = i >> 2, q = i & 3;
            float* d = &Bs[s][r * PITCH + q * 4];
            d[0] = __uint_as_float(f2tf32(rb1.x));
            d[1] = __uint_as_float(f2tf32(rb1.y));
            d[2] = __uint_as_float(f2tf32(rb1.z));
            d[3] = __uint_as_float(f2tf32(rb1.w));
        }
    };

    loadG(0);
    storeS(0);
    __syncthreads();

    for (int c = 0; c < NCHUNK; c++) {
        int s = c & 1;
        if (c < NCHUNK - 1) loadG(c + 1);

        const float* aS = As[s];
        const float* bS = Bs[s];
#pragma unroll
        for (int ks = 0; ks < 2; ks++) {
            int k0 = ks * 8 + lc;
            uint32_t a[2][4];
#pragma unroll
            for (int i = 0; i < 2; i++) {
                int r = wm * 32 + i * 16 + lr;
                a[i][0] = __float_as_uint(aS[r * PITCH + k0]);
                a[i][1] = __float_as_uint(aS[(r + 8) * PITCH + k0]);
                a[i][2] = __float_as_uint(aS[r * PITCH + k0 + 4]);
                a[i][3] = __float_as_uint(aS[(r + 8) * PITCH + k0 + 4]);
            }
#pragma unroll
            for (int j = 0; j < 6; j++) {
                int n = wn * 48 + j * 8 + lr;
                uint32_t b0 = __float_as_uint(bS[n * PITCH + k0]);
                uint32_t b1 = __float_as_uint(bS[n * PITCH + k0 + 4]);
#pragma unroll
                for (int i = 0; i < 2; i++) mma_tf32(acc[i][j], a[i], b0, b1);
            }
        }

        if (c < NCHUNK - 1) storeS(s ^ 1);
        __syncthreads();
    }

    // ---- epilogue ----
#pragma unroll
    for (int i = 0; i < 2; i++) {
        int row = rowBase + wm * 32 + i * 16 + lr;
#pragma unroll
        for (int j = 0; j < 6; j++) {
            int col = colBase + wn * 48 + j * 8 + 2 * lc;
            float bx = __ldg(&bias[col]), by = __ldg(&bias[col + 1]);
            float2 v0, v1;
            v0.x = acc[i][j][0] + bx; v0.y = acc[i][j][1] + by;
            v1.x = acc[i][j][2] + bx; v1.y = acc[i][j][3] + by;
            if (RELU) {
                v0.x = fmaxf(v0.x, 0.f); v0.y = fmaxf(v0.y, 0.f);
                v1.x = fmaxf(v1.x, 0.f); v1.y = fmaxf(v1.y, 0.f);
            }
            *(float2*)(C + (size_t)row * Fq + col) = v0;
            *(float2*)(C + (size_t)(row + 8) * Fq + col) = v1;
        }
    }
}

// ---------------------------------------------------------------------------
extern "C" void kernel_launch(void* const* d_in, const int* in_sizes, int n_in,
                              void* d_out, int out_size) {
    const float* feat_c = (const float*)d_in[0];
    const float* feat_s = (const float*)d_in[1];
    const int*   idx_k1 = (const int*)d_in[2];
    const int*   idx_k2 = (const int*)d_in[3];
    const float* W1     = (const float*)d_in[4];
    const float* b1     = (const float*)d_in[5];
    const float* W2     = (const float*)d_in[6];
    const float* b2     = (const float*)d_in[7];
    float* out = (float*)d_out;

    float* agg; cudaGetSymbolAddress((void**)&agg, g_agg);
    float* h1;  cudaGetSymbolAddress((void**)&h1,  g_h1);
    float* wt1; cudaGetSymbolAddress((void**)&wt1, g_Wt1);
    float* wt2; cudaGetSymbolAddress((void**)&wt2, g_Wt2);

    // prep
    zero_deg_kernel<<<(Bq * NODESQ + 255) / 256, 256>>>();
    hist_kernel<<<(Bq * Mq * Kq + 255) / 256, 256>>>(idx_k1, idx_k2);
    dsc_kernel<<<(Bq * NODESQ + 255) / 256, 256>>>(b1);
    transpose_kernel<<<(Fq * Fq + 255) / 256, 256>>>(W1, W2);

    dim3 ggrid(ROWSQ / TMg, Fq / TNg);   // 256 x 3

    // layer 1
    gather1_kernel<<<ROWSQ / 8, 256>>>(feat_c, feat_s, idx_k1, idx_k2);
    gemm_tf32_kernel<true><<<ggrid, 256>>>(agg, wt1, b1, h1);

    // layer 2
    gather2_kernel<<<ROWSQ / 8, 256>>>(idx_k1, idx_k2);
    gemm_tf32_kernel<false><<<ggrid, 256>>>(agg, wt2, b2, out);
}